// round 16
// baseline (speedup 1.0000x reference)
#include <cuda_runtime.h>
#include <cuda_bf16.h>
#include <cuda_fp16.h>
#include <math.h>
#include <stdint.h>

#define NPIX       65536      // 64 * 32 * 32 pixels
#define KEMB       1024
#define DIM        256
#define HW         1024       // 32*32
#define OUT_ELEMS  16777216   // 64*256*32*32
#define ENC_ELEMS  67108864   // 65536*1024

// ---- device scratch (no allocations allowed) ----
__device__ int     g_idx[NPIX];
__device__ float   g_xsq[NPIX];
__device__ float   g_sx[NPIX];       // per-pixel int8 scale
__device__ float   g_l1x[NPIX];      // per-pixel L1 norm
__device__ float   g_ensq[KEMB];
__device__ float   g_sec[KEMB];      // per-code int8 scale
__device__ int     g_l1emax_i;       // max over codes of L1(e)   (float bits)
__device__ int     g_semax_i;        // max over codes of se      (float bits)
__device__ int     g_counts[KEMB];
__device__ float   g_loss;
__device__ int8_t  g_qa[NPIX * DIM]; // int8(x/sx), transposed [pix][dim]
__device__ int8_t  g_qe[KEMB * DIM]; // int8(e/se), [emb][dim]
__device__ __half  g_dots[(size_t)NPIX * KEMB]; // f16(idot/128)

// ================= PTX helpers (portable: sm_80+) =================
__device__ __forceinline__ uint32_t smem_to_u32(const void* p) {
    uint32_t a;
    asm("{ .reg .u64 t; cvta.to.shared.u64 t, %1; cvt.u32.u64 %0, t; }" : "=r"(a) : "l"(p));
    return a;
}
__device__ __forceinline__ void ldsm_x4(uint32_t& r0, uint32_t& r1, uint32_t& r2,
                                        uint32_t& r3, uint32_t addr) {
    asm volatile("ldmatrix.sync.aligned.m8n8.x4.shared.b16 {%0,%1,%2,%3}, [%4];"
        : "=r"(r0), "=r"(r1), "=r"(r2), "=r"(r3) : "r"(addr));
}
// s8 m16n8k32 IMMA: byte-layout of A/B fragments identical to bf16 m16n8k16
__device__ __forceinline__ void mma_s8(int* c, const uint32_t* a,
                                       uint32_t b0, uint32_t b1) {
    asm volatile("mma.sync.aligned.m16n8k32.row.col.s32.s8.s8.s32 "
        "{%0,%1,%2,%3}, {%4,%5,%6,%7}, {%8,%9}, {%0,%1,%2,%3};"
        : "+r"(c[0]), "+r"(c[1]), "+r"(c[2]), "+r"(c[3])
        : "r"(a[0]), "r"(a[1]), "r"(a[2]), "r"(a[3]), "r"(b0), "r"(b1));
}

// ================= small helper kernels =================
__global__ void vq_init() {
    int t = threadIdx.x;
    if (t < KEMB) g_counts[t] = 0;
    if (t == 0) { g_loss = 0.0f; g_l1emax_i = 0; g_semax_i = 0; }
}

__global__ void vq_ensq(const float* __restrict__ emb) {
    int warp = (blockIdx.x * blockDim.x + threadIdx.x) >> 5;
    int lane = threadIdx.x & 31;
    if (warp >= KEMB) return;
    const float* row = emb + (size_t)warp * DIM;
    float s = 0.f;
    #pragma unroll
    for (int j = 0; j < DIM / 32; j++) { float v = row[lane + 32 * j]; s += v * v; }
    #pragma unroll
    for (int o = 16; o; o >>= 1) s += __shfl_xor_sync(0xffffffffu, s, o);
    if (lane == 0) g_ensq[warp] = s;
}

// per-pixel: ||x||^2 (EXACT same accumulation as passing rounds), max|x|, L1(x)
__global__ void vq_xstat(const float* __restrict__ inp) {
    int b  = blockIdx.x;
    int hw = threadIdx.x;
    const float* base = inp + (size_t)b * DIM * HW + hw;
    float s = 0.f, m = 0.f, l1 = 0.f;
    #pragma unroll 8
    for (int c = 0; c < DIM; c++) {
        float v = base[(size_t)c * HW];
        s = fmaf(v, v, s);
        float a = fabsf(v);
        m = fmaxf(m, a);
        l1 += a;
    }
    int p = b * HW + hw;
    g_xsq[p] = s;
    g_sx[p]  = fmaxf(m * (1.0f / 127.0f), 1e-30f);
    g_l1x[p] = l1;
}

// per-code: int8 quantize + scale + L1; warp per code
__global__ void vq_prep_emb(const float* __restrict__ emb) {
    int code = (blockIdx.x * blockDim.x + threadIdx.x) >> 5;
    int lane = threadIdx.x & 31;
    if (code >= KEMB) return;
    const float4* row4 = (const float4*)(emb + (size_t)code * DIM);
    float4 va = row4[lane * 2], vb = row4[lane * 2 + 1];
    float v[8] = {va.x, va.y, va.z, va.w, vb.x, vb.y, vb.z, vb.w};
    float m = 0.f, l1 = 0.f;
    #pragma unroll
    for (int j = 0; j < 8; j++) { float a = fabsf(v[j]); m = fmaxf(m, a); l1 += a; }
    #pragma unroll
    for (int o = 16; o; o >>= 1) {
        m  = fmaxf(m, __shfl_xor_sync(0xffffffffu, m, o));
        l1 += __shfl_xor_sync(0xffffffffu, l1, o);
    }
    float se = fmaxf(m * (1.0f / 127.0f), 1e-30f);
    if (lane == 0) {
        g_sec[code] = se;
        atomicMax(&g_l1emax_i, __float_as_int(l1));
        atomicMax(&g_semax_i,  __float_as_int(se));
    }
    float inv = 1.0f / se;
    uint32_t w0 = 0, w1 = 0;
    #pragma unroll
    for (int j = 0; j < 4; j++) {
        int q = (int)rintf(v[j] * inv);
        q = max(-127, min(127, q));
        w0 |= ((uint32_t)(uint8_t)(int8_t)q) << (8 * j);
    }
    #pragma unroll
    for (int j = 0; j < 4; j++) {
        int q = (int)rintf(v[4 + j] * inv);
        q = max(-127, min(127, q));
        w1 |= ((uint32_t)(uint8_t)(int8_t)q) << (8 * j);
    }
    *(uint2*)&g_qe[(size_t)code * DIM + lane * 8] = make_uint2(w0, w1);
}

// transpose inp: [b][c][hw] -> [pix][c]; int8 quantize with per-pixel scale
__global__ __launch_bounds__(256)
void vq_prep_a(const float* __restrict__ inp) {
    __shared__ float sm[256][35];
    int b = blockIdx.x >> 5, hw0 = (blockIdx.x & 31) * 32;
    const float* src = inp + (size_t)b * (DIM * HW) + hw0;
    int tid = threadIdx.x;
    #pragma unroll
    for (int pass = 0; pass < 8; pass++) {
        int idx = pass * 256 + tid;          // 0..2047
        int c = idx >> 3, h4 = (idx & 7) * 4;
        float4 v = *(const float4*)&src[(size_t)c * HW + h4];
        sm[c][h4] = v.x; sm[c][h4 + 1] = v.y; sm[c][h4 + 2] = v.z; sm[c][h4 + 3] = v.w;
    }
    __syncthreads();
    int p0 = b * HW + hw0;
    #pragma unroll
    for (int pass = 0; pass < 8; pass++) {
        int idx = pass * 256 + tid;
        int hw = idx >> 6, c4 = (idx & 63) * 4;
        float inv = 1.0f / g_sx[p0 + hw];
        uint32_t w = 0;
        #pragma unroll
        for (int j = 0; j < 4; j++) {
            int q = (int)rintf(sm[c4 + j][hw] * inv);
            q = max(-127, min(127, q));
            w |= ((uint32_t)(uint8_t)(int8_t)q) << (8 * j);
        }
        *(uint32_t*)&g_qa[(size_t)(p0 + hw) * DIM + c4] = w;
    }
}

// ================= phase 1: int8 IMMA GEMM -> f16(idot/128) =================
// CTA = 128 pixels; B tile = 128 codes (8 iterations). stride 272B (conflict-free ldsm).
#define SM_STRIDE 272
#define SM_B_OFF  (128 * SM_STRIDE)             // 34816
#define GEMM_SMEM (SM_B_OFF + 128 * SM_STRIDE)  // 69632 -> 2 CTAs/SM

__global__ __launch_bounds__(256, 2)
void vq_gemm() {
    extern __shared__ char sm[];
    uint32_t smA = smem_to_u32(sm);
    uint32_t smB = smA + SM_B_OFF;
    int tid = threadIdx.x, w = tid >> 5, lane = tid & 31;
    int p0 = blockIdx.x * 128;

    // fill A tile once (128 rows x 256B)
    for (int i = tid; i < 2048; i += 256) {
        int row = i >> 4, q = (i & 15) * 16;
        uint4 v = *(const uint4*)(g_qa + (size_t)(p0 + row) * DIM + q);
        *(uint4*)(sm + row * SM_STRIDE + q) = v;
    }
    __syncthreads();

    // A fragments for all 8 k-steps (32 regs); byte-layout == bf16 m16n8k16 pattern
    uint32_t Af[8][4];
    {
        int lr = lane & 15, lc = lane >> 4;
        uint32_t abase = smA + (w * 16 + lr) * SM_STRIDE + lc * 16;
        #pragma unroll
        for (int s = 0; s < 8; s++)
            ldsm_x4(Af[s][0], Af[s][1], Af[s][2], Af[s][3], abase + s * 32);
    }

    for (int nt = 0; nt < 8; nt++) {
        __syncthreads();   // all warps done with previous B fragments
        for (int i = tid; i < 2048; i += 256) {      // 128 rows x 256B
            int row = i >> 4, q = (i & 15) * 16;
            uint4 v = *(const uint4*)(g_qe + (size_t)(nt * 128 + row) * DIM + q);
            *(uint4*)(sm + SM_B_OFF + row * SM_STRIDE + q) = v;
        }
        __syncthreads();

        int acc[16][4];
        #pragma unroll
        for (int t = 0; t < 16; t++)
            #pragma unroll
            for (int r = 0; r < 4; r++) acc[t][r] = 0;

        #pragma unroll
        for (int s2 = 0; s2 < 8; s2++) {
            #pragma unroll
            for (int tp = 0; tp < 8; tp++) {         // 16 codes per ldsm.x4
                uint32_t b0, b1, b2, b3;
                int code = tp * 16 + ((lane >> 4) << 3) + (lane & 7);
                uint32_t baddr = smB + code * SM_STRIDE + s2 * 32 + ((lane >> 3) & 1) * 16;
                ldsm_x4(b0, b1, b2, b3, baddr);
                mma_s8(acc[2 * tp],     Af[s2], b0, b1);
                mma_s8(acc[2 * tp + 1], Af[s2], b2, b3);
            }
        }

        // store f16(idot/128)   (|idot| <= 256*127*127 -> /128 fits f16 range)
        int r0 = p0 + w * 16 + (lane >> 2);
        int cb = nt * 128 + 2 * (lane & 3);
        #pragma unroll
        for (int t = 0; t < 16; t++) {
            __half2 lo = __floats2half2_rn((float)acc[t][0] * 0.0078125f,
                                           (float)acc[t][1] * 0.0078125f);
            __half2 hi = __floats2half2_rn((float)acc[t][2] * 0.0078125f,
                                           (float)acc[t][3] * 0.0078125f);
            *(__half2*)&g_dots[(size_t)r0 * KEMB + cb + t * 8]       = lo;
            *(__half2*)&g_dots[(size_t)(r0 + 8) * KEMB + cb + t * 8] = hi;
        }
    }
}

// ================= phase 2: candidate refine (exact fp32, ref rounding) ====
__global__ __launch_bounds__(256)
void vq_refine(const float* __restrict__ inp, const float* __restrict__ emb) {
    __shared__ float s_ensq[KEMB];
    __shared__ float s_sec[KEMB];
    __shared__ float s_x[8][256];
    __shared__ int   s_list[8][64];
    __shared__ int   s_cnt[8];

    int tid = threadIdx.x, w = tid >> 5, lane = tid & 31;
    for (int i = tid; i < KEMB; i += 256) { s_ensq[i] = g_ensq[i]; s_sec[i] = g_sec[i]; }
    if (lane == 0) s_cnt[w] = 0;
    __syncthreads();

    int pix = blockIdx.x * 8 + w;
    int b = pix >> 10, hw = pix & 1023;
    float xq  = g_xsq[pix];
    float sxp = g_sx[pix];
    float sp  = sxp * 256.0f;     // d = (xq+ensq) - 2*dot, dot = sx*se*128*hv

    // stage fp32 x row from original [b][c][hw] layout (8 consecutive hw/CTA)
    const float* xsrc = inp + (size_t)b * (DIM * HW) + hw;
    for (int i = lane; i < 256; i += 32) s_x[w][i] = xsrc[(size_t)i * HW];

    // this lane's 32 approx dots
    uint4 q[4];
    const uint4* dp = (const uint4*)(g_dots + (size_t)pix * KEMB) + lane * 4;
    #pragma unroll
    for (int i = 0; i < 4; i++) q[i] = dp[i];
    uint32_t dv[16];
    #pragma unroll
    for (int i = 0; i < 4; i++) {
        dv[4 * i] = q[i].x; dv[4 * i + 1] = q[i].y; dv[4 * i + 2] = q[i].z; dv[4 * i + 3] = q[i].w;
    }

    int cbase = lane * 32;
    float dap[32];
    float dmin = INFINITY;
    #pragma unroll
    for (int r = 0; r < 16; r++) {
        float2 f = __half22float2(*(__half2*)&dv[r]);
        int c0 = cbase + 2 * r;
        float d0 = (xq + s_ensq[c0])     - sp * (s_sec[c0]     * f.x);
        float d1 = (xq + s_ensq[c0 + 1]) - sp * (s_sec[c0 + 1] * f.y);
        dap[2 * r] = d0; dap[2 * r + 1] = d1;
        dmin = fminf(dmin, fminf(d0, d1));
    }
    #pragma unroll
    for (int o = 16; o; o >>= 1) dmin = fminf(dmin, __shfl_xor_sync(0xffffffffu, dmin, o));

    // rigorous superset margin: thr = dmin + 2*B,
    // B = se_max*L1x + sx*L1e_max + 384*sx*se + f16 err  (last terms in slack)
    float l1emax = __int_as_float(g_l1emax_i);
    float semax  = __int_as_float(g_semax_i);
    float thr = dmin + 2.0f * (sxp * l1emax + semax * g_l1x[pix]) + 5.0e-3f;

    #pragma unroll
    for (int r = 0; r < 32; r++) {
        if (dap[r] <= thr) {
            int slot = atomicAdd(&s_cnt[w], 1);
            if (slot < 64) s_list[w][slot] = cbase + r;
        }
    }
    __syncwarp();
    int cnt = s_cnt[w];
    int ovf = (cnt > 64);
    int total = ovf ? KEMB : cnt;

    float bd = INFINITY; int bi = 0x7fffffff;
    for (int base = 0; base < total; base += 32) {
        int ci = base + lane;
        if (ci < total) {
            int cand = ovf ? ci : s_list[w][ci];
            const float* er = emb + (size_t)cand * DIM;
            float acc = 0.f;
            #pragma unroll 8
            for (int k = 0; k < 256; k++) acc = fmaf(s_x[w][k], er[k], acc);
            // ref rounding: fl(fl(||x||^2 + ||e||^2) - 2*x.e)
            float t2  = xq + s_ensq[cand];
            float dct = t2 - 2.0f * acc;
            if (dct < bd || (dct == bd && cand < bi)) { bd = dct; bi = cand; }
        }
    }
    #pragma unroll
    for (int o = 16; o; o >>= 1) {
        float od = __shfl_xor_sync(0xffffffffu, bd, o);
        int   oi = __shfl_xor_sync(0xffffffffu, bi, o);
        if (od < bd || (od == bd && oi < bi)) { bd = od; bi = oi; }
    }
    if (lane == 0) {
        g_idx[pix] = bi;
        atomicAdd(&g_counts[bi], 1);
    }
}

// ================= downstream =================
__global__ __launch_bounds__(256)
void vq_gather(const float* __restrict__ inp, const float* __restrict__ emb,
               float* __restrict__ out) {
    __shared__ float sm[256][33];
    __shared__ int   sidx[32];
    __shared__ float sred[8];

    int tid = threadIdx.x;
    int blk = blockIdx.x;
    int b   = blk >> 5;
    int hw0 = (blk & 31) * 32;
    int n0  = b * HW + hw0;

    if (tid < 32) sidx[tid] = g_idx[n0 + tid];
    __syncthreads();

    #pragma unroll
    for (int it = 0; it < 8; it++) {
        int p = it * 4 + (tid >> 6);
        int c = (tid & 63) * 4;
        float4 v = *(const float4*)&emb[(size_t)sidx[p] * DIM + c];
        sm[c + 0][p] = v.x; sm[c + 1][p] = v.y;
        sm[c + 2][p] = v.z; sm[c + 3][p] = v.w;
    }
    __syncthreads();

    int p  = tid & 31;
    int c0 = (tid >> 5) * 32;
    const float* inp_base = inp + (size_t)b * (DIM * HW) + hw0 + p;
    float*       out_base = out + (size_t)b * (DIM * HW) + hw0 + p;
    float ls = 0.f;
    #pragma unroll
    for (int i = 0; i < 32; i++) {
        int c = c0 + i;
        float o = sm[c][p];
        float x = inp_base[(size_t)c * HW];
        out_base[(size_t)c * HW] = o;
        float d = o - x;
        ls = fmaf(d, d, ls);
    }
    #pragma unroll
    for (int o = 16; o; o >>= 1) ls += __shfl_xor_sync(0xffffffffu, ls, o);
    if ((tid & 31) == 0) sred[tid >> 5] = ls;
    __syncthreads();
    if (tid == 0) {
        float s = 0.f;
        #pragma unroll
        for (int w2 = 0; w2 < 8; w2++) s += sred[w2];
        atomicAdd(&g_loss, s);
    }
}

__global__ void vq_enc(float2* __restrict__ enc) {
    int t  = blockIdx.x * blockDim.x + threadIdx.x;   // < 33554432
    int n  = t >> 9;
    int k2 = (t & 511) << 1;
    int id = g_idx[n];
    float2 v;
    v.x = (id == k2)     ? 1.0f : 0.0f;
    v.y = (id == k2 + 1) ? 1.0f : 0.0f;
    enc[t] = v;
}

__global__ void vq_finalize(float* __restrict__ d_out) {
    __shared__ float sm[32];
    int t = threadIdx.x;
    float p = (float)g_counts[t] * (1.0f / 65536.0f);
    float s = p * logf(p + 1e-10f);
    #pragma unroll
    for (int o = 16; o; o >>= 1) s += __shfl_xor_sync(0xffffffffu, s, o);
    if ((t & 31) == 0) sm[t >> 5] = s;
    __syncthreads();
    if (t < 32) {
        s = sm[t];
        #pragma unroll
        for (int o = 16; o; o >>= 1) s += __shfl_xor_sync(0xffffffffu, s, o);
        if (t == 0) {
            d_out[0]             = 1.25f * g_loss * (1.0f / 16777216.0f);
            d_out[1 + OUT_ELEMS] = expf(-s);
        }
    }
}

extern "C" void kernel_launch(void* const* d_in, const int* in_sizes, int n_in,
                              void* d_out, int out_size) {
    const float* inp = (const float*)d_in[0];   // [64,256,32,32]
    const float* emb = (const float*)d_in[1];   // [1024,256]
    float* out = (float*)d_out;                 // [loss | out | perplexity | encodings]

    cudaFuncSetAttribute(vq_gemm, cudaFuncAttributeMaxDynamicSharedMemorySize, GEMM_SMEM);

    vq_init    <<<1, 1024>>>();
    vq_ensq    <<<128, 256>>>(emb);
    vq_xstat   <<<64, 1024>>>(inp);
    vq_prep_emb<<<128, 256>>>(emb);
    vq_prep_a  <<<2048, 256>>>(inp);
    vq_gemm    <<<NPIX / 128, 256, GEMM_SMEM>>>();
    vq_refine  <<<NPIX / 8, 256>>>(inp, emb);
    vq_gather  <<<2048, 256>>>(inp, emb, out + 1);
    vq_enc     <<<ENC_ELEMS / 2 / 256, 256>>>((float2*)(out + 2 + OUT_ELEMS));
    vq_finalize<<<1, 1024>>>(out);
}

// round 17
// speedup vs baseline: 2.5617x; 2.5617x over previous
#include <cuda_runtime.h>
#include <cuda_bf16.h>
#include <cuda_fp16.h>
#include <math.h>
#include <stdint.h>

#define NPIX       65536      // 64 * 32 * 32 pixels
#define KEMB       1024
#define DIM        256
#define HW         1024       // 32*32
#define OUT_ELEMS  16777216   // 64*256*32*32
#define ENC_ELEMS  67108864   // 65536*1024

// ---- device scratch (no allocations allowed) ----
__device__ int   g_idx[NPIX];
__device__ float g_xsq[NPIX];
__device__ float g_ensq[KEMB];
__device__ int   g_counts[KEMB];
__device__ float g_loss;
__device__ __nv_bfloat16 g_a0[NPIX * DIM];   // bf16(x), transposed [pix][dim]
__device__ __nv_bfloat16 g_e0[KEMB * DIM];   // bf16(e), [emb][dim]
__device__ __half        g_dots[(size_t)NPIX * KEMB]; // approx dots, f16

// ================= PTX helpers (portable: sm_80+) =================
__device__ __forceinline__ uint32_t smem_to_u32(const void* p) {
    uint32_t a;
    asm("{ .reg .u64 t; cvta.to.shared.u64 t, %1; cvt.u32.u64 %0, t; }" : "=r"(a) : "l"(p));
    return a;
}
__device__ __forceinline__ void ldsm_x4(uint32_t& r0, uint32_t& r1, uint32_t& r2,
                                        uint32_t& r3, uint32_t addr) {
    asm volatile("ldmatrix.sync.aligned.m8n8.x4.shared.b16 {%0,%1,%2,%3}, [%4];"
        : "=r"(r0), "=r"(r1), "=r"(r2), "=r"(r3) : "r"(addr));
}
__device__ __forceinline__ void mma_bf16(float* c, const uint32_t* a,
                                         uint32_t b0, uint32_t b1) {
    asm volatile("mma.sync.aligned.m16n8k16.row.col.f32.bf16.bf16.f32 "
        "{%0,%1,%2,%3}, {%4,%5,%6,%7}, {%8,%9}, {%0,%1,%2,%3};"
        : "+f"(c[0]), "+f"(c[1]), "+f"(c[2]), "+f"(c[3])
        : "r"(a[0]), "r"(a[1]), "r"(a[2]), "r"(a[3]), "r"(b0), "r"(b1));
}
#define CP_ASYNC16(dst, src) \
    asm volatile("cp.async.cg.shared.global [%0], [%1], 16;" :: "r"(dst), "l"(src))
#define CP_COMMIT() asm volatile("cp.async.commit_group;" ::: "memory")
#define CP_WAIT(n)  asm volatile("cp.async.wait_group %0;" :: "n"(n) : "memory")

// ================= small helper kernels =================
__global__ void vq_init() {
    int t = threadIdx.x;
    if (t < KEMB) g_counts[t] = 0;
    if (t == 0)   g_loss = 0.0f;
}

__global__ void vq_ensq(const float* __restrict__ emb) {
    int warp = (blockIdx.x * blockDim.x + threadIdx.x) >> 5;
    int lane = threadIdx.x & 31;
    if (warp >= KEMB) return;
    const float* row = emb + (size_t)warp * DIM;
    float s = 0.f;
    #pragma unroll
    for (int j = 0; j < DIM / 32; j++) { float v = row[lane + 32 * j]; s += v * v; }
    #pragma unroll
    for (int o = 16; o; o >>= 1) s += __shfl_xor_sync(0xffffffffu, s, o);
    if (lane == 0) g_ensq[warp] = s;
}

// identical numerics to passing rounds
__global__ void vq_xsq(const float* __restrict__ inp) {
    int b  = blockIdx.x;
    int hw = threadIdx.x;
    const float* base = inp + (size_t)b * DIM * HW + hw;
    float s = 0.f;
    #pragma unroll 8
    for (int c = 0; c < DIM; c++) { float v = base[(size_t)c * HW]; s = fmaf(v, v, s); }
    g_xsq[b * HW + hw] = s;
}

__global__ void vq_prep_emb(const float* __restrict__ emb) {
    int e = blockIdx.x * 256 + threadIdx.x;   // grid 1024 -> 262144
    g_e0[e] = __float2bfloat16(emb[e]);
}

// ---- transpose inp: [b][c][hw] -> [pix][c]; bf16 copy only ----
__global__ __launch_bounds__(256)
void vq_prep_a(const float* __restrict__ inp) {
    __shared__ float sm[256][35];
    int b = blockIdx.x >> 5, hw0 = (blockIdx.x & 31) * 32;
    const float* src = inp + (size_t)b * (DIM * HW) + hw0;
    int tid = threadIdx.x;
    #pragma unroll
    for (int pass = 0; pass < 8; pass++) {
        int idx = pass * 256 + tid;          // 0..2047
        int c = idx >> 3, h4 = (idx & 7) * 4;
        float4 v = *(const float4*)&src[(size_t)c * HW + h4];
        sm[c][h4] = v.x; sm[c][h4 + 1] = v.y; sm[c][h4 + 2] = v.z; sm[c][h4 + 3] = v.w;
    }
    __syncthreads();
    int p0 = b * HW + hw0;
    #pragma unroll
    for (int pass = 0; pass < 8; pass++) {
        int idx = pass * 256 + tid;
        int hw = idx >> 6, c4 = (idx & 63) * 4;
        float v0 = sm[c4][hw], v1 = sm[c4 + 1][hw], v2 = sm[c4 + 2][hw], v3 = sm[c4 + 3][hw];
        size_t o = (size_t)(p0 + hw) * DIM + c4;
        uint32_t lo = (uint32_t)__bfloat16_as_ushort(__float2bfloat16(v0)) |
                      ((uint32_t)__bfloat16_as_ushort(__float2bfloat16(v1)) << 16);
        uint32_t hi = (uint32_t)__bfloat16_as_ushort(__float2bfloat16(v2)) |
                      ((uint32_t)__bfloat16_as_ushort(__float2bfloat16(v3)) << 16);
        *(uint2*)&g_a0[o] = make_uint2(lo, hi);
    }
}

// ================= phase 1: bf16 HMMA GEMM -> f16 dots =================
// CTA = 128 pixels; B = 32 codes x 2 cp.async-double-buffered tiles (32 iters).
// smem = A 128x528 + 2 * (32x528) = 101376 -> 2 CTAs/SM.
#define SM_STRIDE 528
#define SM_B_OFF  67584
#define B_BUF_SZ  (32 * SM_STRIDE)              // 16896
#define GEMM_SMEM (SM_B_OFF + 2 * B_BUF_SZ)     // 101376

__global__ __launch_bounds__(256, 2)
void vq_gemm() {
    extern __shared__ char sm[];
    uint32_t smA = smem_to_u32(sm);
    int tid = threadIdx.x, w = tid >> 5, lane = tid & 31;
    int p0 = blockIdx.x * 128;

    // fill A tile once (128 rows x 512B)
    for (int i = tid; i < 4096; i += 256) {
        int row = i >> 5, q = (i & 31) * 16;
        uint4 v = *(const uint4*)((const char*)g_a0 + (size_t)(p0 + row) * 512 + q);
        *(uint4*)(sm + row * SM_STRIDE + q) = v;
    }

    // prefetch B tile 0 into buffer 0 (32 rows x 512B = 1024 chunks, 4/thread)
    {
        #pragma unroll
        for (int j = 0; j < 4; j++) {
            int idx = tid + 256 * j;
            int row = idx >> 5, q = (idx & 31) * 16;
            CP_ASYNC16(smA + SM_B_OFF + row * SM_STRIDE + q,
                       (const char*)g_e0 + (size_t)row * 512 + q);
        }
        CP_COMMIT();
    }
    __syncthreads();     // A tile visible

    // A fragments for all 16 k-steps (64 regs)
    uint32_t Af[16][4];
    {
        int lr = lane & 15, lc = lane >> 4;
        uint32_t abase = smA + (w * 16 + lr) * SM_STRIDE + lc * 16;
        #pragma unroll
        for (int s = 0; s < 16; s++)
            ldsm_x4(Af[s][0], Af[s][1], Af[s][2], Af[s][3], abase + s * 32);
    }

    int gb = lane >> 3, rl = lane & 7;
    for (int nt = 0; nt < 32; nt++) {
        uint32_t smB = smA + SM_B_OFF + (nt & 1) * B_BUF_SZ;
        // prefetch next tile into the other buffer (last read 2 iters ago,
        // protected by the trailing __syncthreads of iter nt-1)
        if (nt < 31) {
            uint32_t smBn = smA + SM_B_OFF + ((nt + 1) & 1) * B_BUF_SZ;
            #pragma unroll
            for (int j = 0; j < 4; j++) {
                int idx = tid + 256 * j;
                int row = idx >> 5, q = (idx & 31) * 16;
                CP_ASYNC16(smBn + row * SM_STRIDE + q,
                           (const char*)g_e0 + (size_t)((nt + 1) * 32 + row) * 512 + q);
            }
            CP_COMMIT();
            CP_WAIT(1);      // current tile's group complete
        } else {
            CP_WAIT(0);
        }
        __syncthreads();     // all threads' cp.async chunks visible

        float acc[4][4];
        #pragma unroll
        for (int t = 0; t < 4; t++)
            #pragma unroll
            for (int r = 0; r < 4; r++) acc[t][r] = 0.f;

        #pragma unroll
        for (int s2 = 0; s2 < 8; s2++) {
            #pragma unroll
            for (int t = 0; t < 4; t++) {
                uint32_t b0, b1, b2, b3;
                uint32_t baddr = smB + (t * 8 + rl) * SM_STRIDE + s2 * 64 + gb * 16;
                ldsm_x4(b0, b1, b2, b3, baddr);
                mma_bf16(acc[t], Af[2 * s2],     b0, b1);
                mma_bf16(acc[t], Af[2 * s2 + 1], b2, b3);
            }
        }
        __syncthreads();     // done reading this buffer before it is re-prefetched

        // store f16 dots
        int r0 = p0 + w * 16 + (lane >> 2);
        int cb = nt * 32 + 2 * (lane & 3);
        #pragma unroll
        for (int t = 0; t < 4; t++) {
            __half2 lo = __floats2half2_rn(acc[t][0], acc[t][1]);
            __half2 hi = __floats2half2_rn(acc[t][2], acc[t][3]);
            *(__half2*)&g_dots[(size_t)r0 * KEMB + cb + t * 8]       = lo;
            *(__half2*)&g_dots[(size_t)(r0 + 8) * KEMB + cb + t * 8] = hi;
        }
    }
}

// ================= phase 2: candidate refine (exact fp32, ref rounding) ====
__global__ __launch_bounds__(256)
void vq_refine(const float* __restrict__ inp, const float* __restrict__ emb) {
    __shared__ float s_ensq[KEMB];
    __shared__ float s_x[8][256];
    __shared__ int   s_list[8][64];
    __shared__ int   s_cnt[8];

    int tid = threadIdx.x, w = tid >> 5, lane = tid & 31;
    for (int i = tid; i < KEMB; i += 256) s_ensq[i] = g_ensq[i];
    if (lane == 0) s_cnt[w] = 0;
    __syncthreads();

    int pix = blockIdx.x * 8 + w;
    int b = pix >> 10, hw = pix & 1023;
    float xq = g_xsq[pix];

    // stage fp32 x row from original [b][c][hw] layout (8 consecutive hw/CTA)
    const float* xsrc = inp + (size_t)b * (DIM * HW) + hw;
    for (int i = lane; i < 256; i += 32) s_x[w][i] = xsrc[(size_t)i * HW];

    // this lane's 32 approx dots (f16)
    uint4 q[4];
    const uint4* dp = (const uint4*)(g_dots + (size_t)pix * KEMB) + lane * 4;
    #pragma unroll
    for (int i = 0; i < 4; i++) q[i] = dp[i];
    uint32_t dv[16];
    #pragma unroll
    for (int i = 0; i < 4; i++) {
        dv[4 * i] = q[i].x; dv[4 * i + 1] = q[i].y; dv[4 * i + 2] = q[i].z; dv[4 * i + 3] = q[i].w;
    }

    int cbase = lane * 32;
    float dap[32];
    float dmin = INFINITY;
    #pragma unroll
    for (int r = 0; r < 16; r++) {
        float2 f = __half22float2(*(__half2*)&dv[r]);
        float d0 = (xq + s_ensq[cbase + 2 * r])     - 2.0f * f.x;
        float d1 = (xq + s_ensq[cbase + 2 * r + 1]) - 2.0f * f.y;
        dap[2 * r] = d0; dap[2 * r + 1] = d1;
        dmin = fminf(dmin, fminf(d0, d1));
    }
    #pragma unroll
    for (int o = 16; o; o >>= 1) dmin = fminf(dmin, __shfl_xor_sync(0xffffffffu, dmin, o));

    // provable pruning threshold (bf16 screen, r9/r13-proven):
    //  |d_approx - d_ref| <= 2*(2^-8 * ||x|| * 0.015625 + 2.5e-4 f16 + slack)
    float thr = dmin + 2.44140625e-4f * sqrtf(xq) + 1.2e-3f;

    #pragma unroll
    for (int r = 0; r < 32; r++) {
        if (dap[r] <= thr) {
            int slot = atomicAdd(&s_cnt[w], 1);
            if (slot < 64) s_list[w][slot] = cbase + r;
        }
    }
    __syncwarp();
    int cnt = s_cnt[w];
    int ovf = (cnt > 64);
    int total = ovf ? KEMB : cnt;

    float bd = INFINITY; int bi = 0x7fffffff;
    for (int base = 0; base < total; base += 32) {
        int ci = base + lane;
        if (ci < total) {
            int cand = ovf ? ci : s_list[w][ci];
            const float* er = emb + (size_t)cand * DIM;
            float acc = 0.f;
            #pragma unroll 8
            for (int k = 0; k < 256; k++) acc = fmaf(s_x[w][k], er[k], acc);
            // ref rounding: fl(fl(||x||^2 + ||e||^2) - 2*x.e)
            float t2  = xq + s_ensq[cand];
            float dct = t2 - 2.0f * acc;
            if (dct < bd || (dct == bd && cand < bi)) { bd = dct; bi = cand; }
        }
    }
    #pragma unroll
    for (int o = 16; o; o >>= 1) {
        float od = __shfl_xor_sync(0xffffffffu, bd, o);
        int   oi = __shfl_xor_sync(0xffffffffu, bi, o);
        if (od < bd || (od == bd && oi < bi)) { bd = od; bi = oi; }
    }
    if (lane == 0) {
        g_idx[pix] = bi;
        atomicAdd(&g_counts[bi], 1);
    }
}

// ================= downstream =================
__global__ __launch_bounds__(256)
void vq_gather(const float* __restrict__ inp, const float* __restrict__ emb,
               float* __restrict__ out) {
    __shared__ float sm[256][33];
    __shared__ int   sidx[32];
    __shared__ float sred[8];

    int tid = threadIdx.x;
    int blk = blockIdx.x;
    int b   = blk >> 5;
    int hw0 = (blk & 31) * 32;
    int n0  = b * HW + hw0;

    if (tid < 32) sidx[tid] = g_idx[n0 + tid];
    __syncthreads();

    #pragma unroll
    for (int it = 0; it < 8; it++) {
        int p = it * 4 + (tid >> 6);
        int c = (tid & 63) * 4;
        float4 v = *(const float4*)&emb[(size_t)sidx[p] * DIM + c];
        sm[c + 0][p] = v.x; sm[c + 1][p] = v.y;
        sm[c + 2][p] = v.z; sm[c + 3][p] = v.w;
    }
    __syncthreads();

    int p  = tid & 31;
    int c0 = (tid >> 5) * 32;
    const float* inp_base = inp + (size_t)b * (DIM * HW) + hw0 + p;
    float*       out_base = out + (size_t)b * (DIM * HW) + hw0 + p;
    float ls = 0.f;
    #pragma unroll
    for (int i = 0; i < 32; i++) {
        int c = c0 + i;
        float o = sm[c][p];
        float x = inp_base[(size_t)c * HW];
        out_base[(size_t)c * HW] = o;
        float d = o - x;
        ls = fmaf(d, d, ls);
    }
    #pragma unroll
    for (int o = 16; o; o >>= 1) ls += __shfl_xor_sync(0xffffffffu, ls, o);
    if ((tid & 31) == 0) sred[tid >> 5] = ls;
    __syncthreads();
    if (tid == 0) {
        float s = 0.f;
        #pragma unroll
        for (int w2 = 0; w2 < 8; w2++) s += sred[w2];
        atomicAdd(&g_loss, s);
    }
}

__global__ void vq_enc(float2* __restrict__ enc) {
    int t  = blockIdx.x * blockDim.x + threadIdx.x;   // < 33554432
    int n  = t >> 9;
    int k2 = (t & 511) << 1;
    int id = g_idx[n];
    float2 v;
    v.x = (id == k2)     ? 1.0f : 0.0f;
    v.y = (id == k2 + 1) ? 1.0f : 0.0f;
    enc[t] = v;
}

__global__ void vq_finalize(float* __restrict__ d_out) {
    __shared__ float sm[32];
    int t = threadIdx.x;
    float p = (float)g_counts[t] * (1.0f / 65536.0f);
    float s = p * logf(p + 1e-10f);
    #pragma unroll
    for (int o = 16; o; o >>= 1) s += __shfl_xor_sync(0xffffffffu, s, o);
    if ((t & 31) == 0) sm[t >> 5] = s;
    __syncthreads();
    if (t < 32) {
        s = sm[t];
        #pragma unroll
        for (int o = 16; o; o >>= 1) s += __shfl_xor_sync(0xffffffffu, s, o);
        if (t == 0) {
            d_out[0]             = 1.25f * g_loss * (1.0f / 16777216.0f);
            d_out[1 + OUT_ELEMS] = expf(-s);
        }
    }
}

extern "C" void kernel_launch(void* const* d_in, const int* in_sizes, int n_in,
                              void* d_out, int out_size) {
    const float* inp = (const float*)d_in[0];   // [64,256,32,32]
    const float* emb = (const float*)d_in[1];   // [1024,256]
    float* out = (float*)d_out;                 // [loss | out | perplexity | encodings]

    cudaFuncSetAttribute(vq_gemm, cudaFuncAttributeMaxDynamicSharedMemorySize, GEMM_SMEM);

    // NOTE: launch order puts vq_gemm at index 3 so the ncu capture
    // (which has empirically profiled the 4th launch every round) finally
    // lands on the GEMM. Dependency-safe: gemm needs only prep_emb/prep_a.
    vq_init    <<<1, 1024>>>();
    vq_prep_emb<<<1024, 256>>>(emb);
    vq_prep_a  <<<2048, 256>>>(inp);
    vq_gemm    <<<NPIX / 128, 256, GEMM_SMEM>>>();
    vq_ensq    <<<128, 256>>>(emb);
    vq_xsq     <<<64, 1024>>>(inp);
    vq_refine  <<<NPIX / 8, 256>>>(inp, emb);
    vq_gather  <<<2048, 256>>>(inp, emb, out + 1);
    vq_enc     <<<ENC_ELEMS / 2 / 256, 256>>>((float2*)(out + 2 + OUT_ELEMS));
    vq_finalize<<<1, 1024>>>(out);
}